// round 1
// baseline (speedup 1.0000x reference)
#include <cuda_runtime.h>
#include <cstdint>

#define TSEQ  512
#define BATCH 64
#define EMBD  512
#define HIDD  1024
#define G4    4096   // 4*HIDD

// ---------------- scratch (static __device__ arrays; no allocation) ---------
// xp[d][t][gate_row][b]  fp32
__device__ float g_xp[(size_t)2 * TSEQ * G4 * BATCH];          // 1.07 GB
// h history [d][t][u][b] (backward stored already time-reversed)
__device__ float g_hist[(size_t)2 * TSEQ * HIDD * BATCH];      // 268 MB
// ping-pong h buffers [d][buf][u*64+b]
__device__ float g_hbuf[4 * HIDD * BATCH];
// cell state [d][u*64+b]
__device__ float g_c[2 * HIDD * BATCH];

// ---------------- f32x2 helpers --------------------------------------------
typedef unsigned long long u64;

__device__ __forceinline__ u64 dup2(float x) {
    u64 r; unsigned xi = __float_as_uint(x);
    asm("mov.b64 %0, {%1, %1};" : "=l"(r) : "r"(xi));
    return r;
}
__device__ __forceinline__ void fma2(u64 &d, u64 a, u64 b) {
    asm("fma.rn.f32x2 %0, %1, %2, %0;" : "+l"(d) : "l"(a), "l"(b));
}
__device__ __forceinline__ float lo32(u64 v) { return __uint_as_float((unsigned)(v & 0xffffffffull)); }
__device__ __forceinline__ float hi32(u64 v) { return __uint_as_float((unsigned)(v >> 32)); }

__device__ __forceinline__ float sigmoidf_(float x) { return 1.0f / (1.0f + expf(-x)); }

// ---------------- init: zero h0/c0 (must re-run every graph replay) ---------
__global__ void init_kernel() {
    int idx = blockIdx.x * 1024 + threadIdx.x;
    if (idx < 4 * HIDD * BATCH) g_hbuf[idx] = 0.0f;
    if (idx < 2 * HIDD * BATCH) g_c[idx]   = 0.0f;
}

// ---------------- x-projection: xp[d][t][g][b] = Wih[g,:]·emb[src] + biases -
// block: 64 gate rows x 64 batch, K = EMBD, 256 threads, thread tile 4x4 (f32x2)
__global__ __launch_bounds__(256) void xproj_kernel(
    const int*   __restrict__ src,
    const float* __restrict__ emb,
    const float* __restrict__ Wih_f, const float* __restrict__ Wih_b,
    const float* __restrict__ bih_f, const float* __restrict__ bhh_f,
    const float* __restrict__ bih_b, const float* __restrict__ bhh_b)
{
    __shared__ float sW[64 * 36];   // [row][k] padded row stride 36
    __shared__ float sX[32 * 64];   // [k][b]
    __shared__ int   sIdx[64];

    const int tid = threadIdx.x;
    const int gt  = blockIdx.x;    // gate-row tile (64 rows)
    const int t   = blockIdx.y;
    const int d   = blockIdx.z;

    const float* Wih = d ? Wih_b : Wih_f;
    const int t_src  = d ? (TSEQ - 1 - t) : t;

    if (tid < 64) sIdx[tid] = src[t_src * BATCH + tid];
    __syncthreads();

    // W loader mapping: 4 threads per row, 2 float4 each
    const int wr = tid >> 2;            // 0..63 (relative row)
    const int wq = tid & 3;             // 0..3
    const float* wgp = Wih + (size_t)(gt * 64 + wr) * EMBD;
    // X loader mapping: one thread per batch column, 8 consecutive k
    const int xn = tid & 63;
    const int xq = tid >> 6;            // 0..3
    const int sidx = sIdx[xn];
    const float* erow = emb + (size_t)sidx * EMBD;
    const bool xzero = (sidx == 0);     // emb_w[0] := 0 rule

    const int i = tid >> 4;             // 0..15 (row group)
    const int j = tid & 15;             // 0..15 (4-batch group)

    u64 acc[4][2];
#pragma unroll
    for (int g = 0; g < 4; ++g) { acc[g][0] = 0ull; acc[g][1] = 0ull; }

    float4 wreg0, wreg1, xreg0, xreg1;
    // prologue: chunk 0 into registers
    wreg0 = *(const float4*)(wgp + wq * 4);
    wreg1 = *(const float4*)(wgp + wq * 4 + 16);
    if (xzero) { xreg0 = make_float4(0.f,0.f,0.f,0.f); xreg1 = xreg0; }
    else { xreg0 = *(const float4*)(erow + xq * 8); xreg1 = *(const float4*)(erow + xq * 8 + 4); }

    const int NC = EMBD / 32;
#pragma unroll 1
    for (int ch = 0; ch < NC; ++ch) {
        // stage current chunk into smem
        *(float4*)&sW[wr * 36 + wq * 4]      = wreg0;
        *(float4*)&sW[wr * 36 + wq * 4 + 16] = wreg1;
        {
            const float* x0 = (const float*)&xreg0;
            const float* x1 = (const float*)&xreg1;
#pragma unroll
            for (int s2 = 0; s2 < 4; ++s2) {
                sX[(xq * 8 + s2)     * 64 + xn] = x0[s2];
                sX[(xq * 8 + 4 + s2) * 64 + xn] = x1[s2];
            }
        }
        __syncthreads();
        // prefetch next chunk
        if (ch + 1 < NC) {
            int k0 = (ch + 1) * 32;
            wreg0 = *(const float4*)(wgp + k0 + wq * 4);
            wreg1 = *(const float4*)(wgp + k0 + wq * 4 + 16);
            if (xzero) { xreg0 = make_float4(0.f,0.f,0.f,0.f); xreg1 = xreg0; }
            else { xreg0 = *(const float4*)(erow + k0 + xq * 8);
                   xreg1 = *(const float4*)(erow + k0 + xq * 8 + 4); }
        }
        // compute 32 k-steps
#pragma unroll
        for (int kb = 0; kb < 8; ++kb) {
            const int k4 = kb * 4;
            float4 w0 = *(const float4*)&sW[(i     ) * 36 + k4];
            float4 w1 = *(const float4*)&sW[(i + 16) * 36 + k4];
            float4 w2 = *(const float4*)&sW[(i + 32) * 36 + k4];
            float4 w3 = *(const float4*)&sW[(i + 48) * 36 + k4];
            const float* p0 = (const float*)&w0;
            const float* p1 = (const float*)&w1;
            const float* p2 = (const float*)&w2;
            const float* p3 = (const float*)&w3;
#pragma unroll
            for (int kk = 0; kk < 4; ++kk) {
                const u64* hx = (const u64*)&sX[(k4 + kk) * 64 + 4 * j];
                u64 h0 = hx[0], h1 = hx[1];
                u64 a;
                a = dup2(p0[kk]); fma2(acc[0][0], a, h0); fma2(acc[0][1], a, h1);
                a = dup2(p1[kk]); fma2(acc[1][0], a, h0); fma2(acc[1][1], a, h1);
                a = dup2(p2[kk]); fma2(acc[2][0], a, h0); fma2(acc[2][1], a, h1);
                a = dup2(p3[kk]); fma2(acc[3][0], a, h0); fma2(acc[3][1], a, h1);
            }
        }
        __syncthreads();
    }

    const float* bih = d ? bih_b : bih_f;
    const float* bhh = d ? bhh_b : bhh_f;
    float* xp = g_xp + (size_t)(d * TSEQ + t) * G4 * BATCH;
#pragma unroll
    for (int g = 0; g < 4; ++g) {
        int row = gt * 64 + i + g * 16;
        float bias = bih[row] + bhh[row];
        float4 o;
        o.x = lo32(acc[g][0]) + bias;
        o.y = hi32(acc[g][0]) + bias;
        o.z = lo32(acc[g][1]) + bias;
        o.w = hi32(acc[g][1]) + bias;
        *(float4*)&xp[(size_t)row * BATCH + 4 * j] = o;
    }
}

// ---------------- one recurrent step, both directions -----------------------
// block = 16 hidden units x 4 gate variants (64 rows) x 64 batch; grid (64, 2)
// each thread ends up holding i,f,g,o for its (u,b) -> pointwise LSTM in-block
__global__ __launch_bounds__(256) void step_kernel(
    const float* __restrict__ Whh_f, const float* __restrict__ Whh_b, int t)
{
    __shared__ float sW[64 * 36];
    __shared__ float sX[32 * 64];

    const int tid = threadIdx.x;
    const int ut  = blockIdx.x;       // 0..63 -> 16 hidden units each
    const int d   = blockIdx.y;
    const int u0  = ut * 16;

    const float* Whh  = d ? Whh_b : Whh_f;
    const float* hprev = g_hbuf + ((size_t)d * 2 + (t & 1))       * (HIDD * BATCH);
    float*       hnext = g_hbuf + ((size_t)d * 2 + ((t + 1) & 1)) * (HIDD * BATCH);
    float*       cbuf  = g_c    + (size_t)d * (HIDD * BATCH);

    // W loader: relative row wr -> global row (wr/16)*HIDD + u0 + (wr%16)
    const int wr = tid >> 2;
    const int wq = tid & 3;
    const int wrow = (wr >> 4) * HIDD + u0 + (wr & 15);
    const float* wgp = Whh + (size_t)wrow * HIDD;
    // X loader: 2 rows x float4 per thread
    const int xk = tid >> 4;          // 0..15
    const int xq = tid & 15;          // 0..15

    const int i = tid >> 4;
    const int j = tid & 15;

    u64 acc[4][2];
#pragma unroll
    for (int g = 0; g < 4; ++g) { acc[g][0] = 0ull; acc[g][1] = 0ull; }

    float4 wreg0, wreg1, xreg0, xreg1;
    wreg0 = *(const float4*)(wgp + wq * 4);
    wreg1 = *(const float4*)(wgp + wq * 4 + 16);
    xreg0 = *(const float4*)&hprev[(size_t)(xk)      * 64 + 4 * xq];
    xreg1 = *(const float4*)&hprev[(size_t)(xk + 16) * 64 + 4 * xq];

    const int NC = HIDD / 32;
#pragma unroll 1
    for (int ch = 0; ch < NC; ++ch) {
        *(float4*)&sW[wr * 36 + wq * 4]      = wreg0;
        *(float4*)&sW[wr * 36 + wq * 4 + 16] = wreg1;
        *(float4*)&sX[(xk)      * 64 + 4 * xq] = xreg0;
        *(float4*)&sX[(xk + 16) * 64 + 4 * xq] = xreg1;
        __syncthreads();
        if (ch + 1 < NC) {
            int k0 = (ch + 1) * 32;
            wreg0 = *(const float4*)(wgp + k0 + wq * 4);
            wreg1 = *(const float4*)(wgp + k0 + wq * 4 + 16);
            xreg0 = *(const float4*)&hprev[(size_t)(k0 + xk)      * 64 + 4 * xq];
            xreg1 = *(const float4*)&hprev[(size_t)(k0 + xk + 16) * 64 + 4 * xq];
        }
#pragma unroll
        for (int kb = 0; kb < 8; ++kb) {
            const int k4 = kb * 4;
            float4 w0 = *(const float4*)&sW[(i     ) * 36 + k4];
            float4 w1 = *(const float4*)&sW[(i + 16) * 36 + k4];
            float4 w2 = *(const float4*)&sW[(i + 32) * 36 + k4];
            float4 w3 = *(const float4*)&sW[(i + 48) * 36 + k4];
            const float* p0 = (const float*)&w0;
            const float* p1 = (const float*)&w1;
            const float* p2 = (const float*)&w2;
            const float* p3 = (const float*)&w3;
#pragma unroll
            for (int kk = 0; kk < 4; ++kk) {
                const u64* hx = (const u64*)&sX[(k4 + kk) * 64 + 4 * j];
                u64 h0 = hx[0], h1 = hx[1];
                u64 a;
                a = dup2(p0[kk]); fma2(acc[0][0], a, h0); fma2(acc[0][1], a, h1);
                a = dup2(p1[kk]); fma2(acc[1][0], a, h0); fma2(acc[1][1], a, h1);
                a = dup2(p2[kk]); fma2(acc[2][0], a, h0); fma2(acc[2][1], a, h1);
                a = dup2(p3[kk]); fma2(acc[3][0], a, h0); fma2(acc[3][1], a, h1);
            }
        }
        __syncthreads();
    }

    // ---- pointwise LSTM update (acc[v] = gate v for u = u0+i, b = 4j..4j+3)
    const float* xp = g_xp + (size_t)(d * TSEQ + t) * G4 * BATCH;
    const int u = u0 + i;
    float gates[4][4];
#pragma unroll
    for (int v = 0; v < 4; ++v) {
        float4 xv = *(const float4*)&xp[(size_t)(v * HIDD + u) * BATCH + 4 * j];
        gates[v][0] = lo32(acc[v][0]) + xv.x;
        gates[v][1] = hi32(acc[v][0]) + xv.y;
        gates[v][2] = lo32(acc[v][1]) + xv.z;
        gates[v][3] = hi32(acc[v][1]) + xv.w;
    }
    float4 cv = *(float4*)&cbuf[(size_t)u * BATCH + 4 * j];
    float* cl = (float*)&cv;
    float4 hv;
    float* hl = (float*)&hv;
#pragma unroll
    for (int l = 0; l < 4; ++l) {
        float ig = sigmoidf_(gates[0][l]);
        float fg = sigmoidf_(gates[1][l]);
        float gg = tanhf(gates[2][l]);
        float og = sigmoidf_(gates[3][l]);
        float cn = fg * cl[l] + ig * gg;
        cl[l] = cn;
        hl[l] = og * tanhf(cn);
    }
    *(float4*)&cbuf [(size_t)u * BATCH + 4 * j] = cv;
    *(float4*)&hnext[(size_t)u * BATCH + 4 * j] = hv;
    const int t_out = d ? (TSEQ - 1 - t) : t;
    *(float4*)&g_hist[((size_t)(d * TSEQ + t_out) * HIDD + u) * BATCH + 4 * j] = hv;
}

// ---------------- combine: out[b][t][h] = hf[t][h][b] + hb[t][h][b] ---------
__global__ __launch_bounds__(256) void combine_kernel(float* __restrict__ out)
{
    __shared__ float s[128 * 65];
    const int uc  = blockIdx.x;   // 0..7 (128 hidden units each)
    const int t   = blockIdx.y;
    const int tid = threadIdx.x;
    const float* hf = g_hist + (size_t)t          * HIDD * BATCH;
    const float* hb = g_hist + (size_t)(TSEQ + t) * HIDD * BATCH;
    for (int x = tid; x < 128 * 64; x += 256) {
        int uu = x >> 6, b = x & 63;
        int u = uc * 128 + uu;
        s[uu * 65 + b] = hf[(size_t)u * BATCH + b] + hb[(size_t)u * BATCH + b];
    }
    __syncthreads();
    for (int x = tid; x < 128 * 64; x += 256) {
        int b = x >> 7, uu = x & 127;
        out[((size_t)b * TSEQ + t) * HIDD + uc * 128 + uu] = s[uu * 65 + b];
    }
}

// ---------------- launch -----------------------------------------------------
extern "C" void kernel_launch(void* const* d_in, const int* in_sizes, int n_in,
                              void* d_out, int out_size)
{
    const int*   src   = (const int*)  d_in[0];
    const float* emb   = (const float*)d_in[1];
    const float* Wih_f = (const float*)d_in[2];
    const float* Whh_f = (const float*)d_in[3];
    const float* bih_f = (const float*)d_in[4];
    const float* bhh_f = (const float*)d_in[5];
    const float* Wih_b = (const float*)d_in[6];
    const float* Whh_b = (const float*)d_in[7];
    const float* bih_b = (const float*)d_in[8];
    const float* bhh_b = (const float*)d_in[9];

    init_kernel<<<256, 1024>>>();
    xproj_kernel<<<dim3(64, 512, 2), 256>>>(src, emb, Wih_f, Wih_b,
                                            bih_f, bhh_f, bih_b, bhh_b);
    for (int t = 0; t < TSEQ; ++t)
        step_kernel<<<dim3(64, 2), 256>>>(Whh_f, Whh_b, t);
    combine_kernel<<<dim3(8, 512), 256>>>((float*)d_out);
}